// round 15
// baseline (speedup 1.0000x reference)
#include <cuda_runtime.h>
#include <cuda_bf16.h>
#include <cstdint>
#include <math.h>

#define NE      800000
#define NNODE   50000

// ---------------- scratch (static device arrays; no allocation) ----------------
__device__ float g_UV[(size_t)NNODE * 320];   // [n][0:160]=U=z@W1, [160:320]=V=z@W2
__device__ float g_G1[(size_t)NNODE * 128];   // [n][0:64]=P, [64:128]=R
__device__ float g_G2[(size_t)NNODE * 128];   // [n][0:64]=Q, [64:128]=S
__device__ int   g_cnt[NNODE];
__device__ int   g_off[NNODE];
__device__ int   g_perm[NE];
__device__ int   g_esrc[NE];
__device__ int   g_edst[NE];

// ---------------- kernel A (node GEMM, persistent) ----------------
#define A_THR  512
#define A_TILE 64
#define A_NT   ((NNODE + A_TILE - 1) / A_TILE)
#define A_ZSTR 144
#define A_WSTR 1168
#define A_ZH   0
#define A_ZL   (A_ZH + 64 * A_ZSTR)
#define A_WH   (A_ZL + 64 * A_ZSTR)
#define A_WL   (A_WH + 64 * A_WSTR)
#define A_SMEM (A_WL + 64 * A_WSTR)              // 167936

// ---------------- kernel F ----------------
#define F_THR   256
#define F_TILE  64
#define F_NT    (NE / F_TILE)                    // 12500
#define F_ESTR  80
#define F_WSTR  336
#define F_DSTR  168
#define F_WH    0
#define F_WL    (F_WH + 32 * F_WSTR)
#define F_BIAS  (F_WL + 32 * F_WSTR)
#define F_LSIG  (F_BIAS + 640)
#define F_LSP   (F_LSIG + 4096)
#define F_BF    (F_LSP + 4096)
#define F_BS    (F_BF + 256)
#define F_UNI   (F_BS + 256)
#define F_EH    (F_UNI)
#define F_EL    (F_UNI + 64 * F_ESTR)
#define F_SMEM  (F_UNI + 64 * F_DSTR * 4)        // 73856 -> 3 CTAs/SM

static __device__ __forceinline__ uint32_t smem_u32(const void* p) {
    uint32_t a;
    asm("{ .reg .u64 t; cvta.to.shared.u64 t, %1; cvt.u32.u64 %0, t; }" : "=r"(a) : "l"(p));
    return a;
}
static __device__ __forceinline__ void ldm_x4(uint32_t* r, uint32_t addr) {
    asm volatile("ldmatrix.sync.aligned.m8n8.x4.shared.b16 {%0,%1,%2,%3}, [%4];"
                 : "=r"(r[0]), "=r"(r[1]), "=r"(r[2]), "=r"(r[3]) : "r"(addr));
}
static __device__ __forceinline__ void ldm_x2t(uint32_t* r, uint32_t addr) {
    asm volatile("ldmatrix.sync.aligned.m8n8.x2.trans.shared.b16 {%0,%1}, [%2];"
                 : "=r"(r[0]), "=r"(r[1]) : "r"(addr));
}
static __device__ __forceinline__ void mma_bf16(float* c, const uint32_t* a, const uint32_t* b) {
    asm volatile("mma.sync.aligned.m16n8k16.row.col.f32.bf16.bf16.f32 "
                 "{%0,%1,%2,%3}, {%4,%5,%6,%7}, {%8,%9}, {%0,%1,%2,%3};"
                 : "+f"(c[0]), "+f"(c[1]), "+f"(c[2]), "+f"(c[3])
                 : "r"(a[0]), "r"(a[1]), "r"(a[2]), "r"(a[3]), "r"(b[0]), "r"(b[1]));
}
static __device__ __forceinline__ void split2(float x0, float x1, uint32_t& hi, uint32_t& lo) {
    uint32_t h;
    asm("cvt.rn.bf16x2.f32 %0, %1, %2;" : "=r"(h) : "f"(x1), "f"(x0));
    float h0 = __uint_as_float(h << 16);
    float h1 = __uint_as_float(h & 0xFFFF0000u);
    uint32_t l;
    asm("cvt.rn.bf16x2.f32 %0, %1, %2;" : "=r"(l) : "f"(x1 - h1), "f"(x0 - h0));
    hi = h; lo = l;
}
static __device__ __forceinline__ float* scratch_ptr(int row, int j) {
    if (j < 320) return g_UV + (size_t)row * 320 + j;
    if (j < 448) return g_G1 + (size_t)row * 128 + (j - 320);
    return g_G2 + (size_t)row * 128 + (j - 448);
}
static __device__ __forceinline__ float lut_eval(const float2* tab, float x) {
    float tp = fmaf(x, 512.0f / 20.0f, 256.0f);
    tp = fminf(fmaxf(tp, 0.0f), 511.5f);
    const float2 c = tab[(int)tp];
    return fmaf(tp, c.y, c.x);
}

// =====================================================================
// Sort kernels: counting sort of edges by dst
// =====================================================================
__global__ void sort_zero_kernel() {
    const int i = blockIdx.x * 256 + threadIdx.x;
    if (i < NNODE) g_cnt[i] = 0;
}
__global__ void sort_hist_kernel(const int* __restrict__ dstp) {
    const int e = blockIdx.x * 256 + threadIdx.x;
    if (e < NE) atomicAdd(&g_cnt[dstp[e]], 1);
}
__global__ __launch_bounds__(1024) void sort_scan_kernel() {
    __shared__ int part[1024];
    const int tid = threadIdx.x;
    const int CH = (NNODE + 1023) / 1024;
    const int base = tid * CH;
    int sum = 0;
    for (int i = 0; i < CH; i++) {
        const int idx = base + i;
        if (idx < NNODE) sum += g_cnt[idx];
    }
    part[tid] = sum;
    __syncthreads();
    for (int d = 1; d < 1024; d <<= 1) {
        const int v = (tid >= d) ? part[tid - d] : 0;
        __syncthreads();
        part[tid] += v;
        __syncthreads();
    }
    int run = (tid == 0) ? 0 : part[tid - 1];
    for (int i = 0; i < CH; i++) {
        const int idx = base + i;
        if (idx < NNODE) {
            g_off[idx] = run;
            run += g_cnt[idx];
        }
    }
}
__global__ void sort_scatter_kernel(const int* __restrict__ srcp,
                                    const int* __restrict__ dstp) {
    const int e = blockIdx.x * 256 + threadIdx.x;
    if (e < NE) {
        const int d = dstp[e];
        const int pos = atomicAdd(&g_off[d], 1);
        g_perm[pos] = e;
        g_esrc[pos] = srcp[e];
        g_edst[pos] = d;
    }
}

// =====================================================================
// Kernel A (persistent): [NNODE,64] @ BigW[64,576] -> UV | G1 | G2
// =====================================================================
__global__ __launch_bounds__(A_THR, 1)
void node_gemm_kernel(const float* __restrict__ z,
                      const float* __restrict__ Wffw,
                      const float* __restrict__ Wf,
                      const float* __restrict__ Ws)
{
    extern __shared__ char sm[];
    const uint32_t sb = smem_u32(sm);
    const int tid = threadIdx.x, wid = tid >> 5, lane = tid & 31;
    const int mi = wid >> 2, ni = wid & 3;

    for (int idx = tid; idx < 64 * 576; idx += A_THR) {
        const int k = idx / 576, j = idx - k * 576;
        float w;
        if (j < 160)      w = Wffw[k * 160 + j];
        else if (j < 320) w = Wffw[(64 + k) * 160 + (j - 160)];
        else if (j < 384) w = Wf[k * 64 + (j - 320)];
        else if (j < 448) w = Ws[k * 64 + (j - 384)];
        else if (j < 512) w = Wf[(64 + k) * 64 + (j - 448)];
        else              w = Ws[(64 + k) * 64 + (j - 512)];
        const __nv_bfloat16 h = __float2bfloat16(w);
        const __nv_bfloat16 l = __float2bfloat16(w - __bfloat162float(h));
        *reinterpret_cast<__nv_bfloat16*>(sm + A_WH + k * A_WSTR + j * 2) = h;
        *reinterpret_cast<__nv_bfloat16*>(sm + A_WL + k * A_WSTR + j * 2) = l;
    }

    const int r = tid >> 3, cq = (tid & 7) * 8;

    float4 va = make_float4(0.f, 0.f, 0.f, 0.f), vb = va;
    int t = blockIdx.x;
    if (t < A_NT) {
        const int grow = t * A_TILE + r;
        if (grow < NNODE) {
            const float4* zr = reinterpret_cast<const float4*>(z + (size_t)grow * 64 + cq);
            va = zr[0]; vb = zr[1];
        }
    }

    for (; t < A_NT; t += gridDim.x) {
        __syncthreads();

        {
            uint32_t* zh = reinterpret_cast<uint32_t*>(sm + A_ZH + r * A_ZSTR + cq * 2);
            uint32_t* zl = reinterpret_cast<uint32_t*>(sm + A_ZL + r * A_ZSTR + cq * 2);
            uint32_t h0, l0, h1, l1;
            split2(va.x, va.y, h0, l0); split2(va.z, va.w, h1, l1);
            zh[0] = h0; zh[1] = h1; zl[0] = l0; zl[1] = l1;
            split2(vb.x, vb.y, h0, l0); split2(vb.z, vb.w, h1, l1);
            zh[2] = h0; zh[3] = h1; zl[2] = l0; zl[3] = l1;
        }
        __syncthreads();

        const int tn = t + gridDim.x;
        va = make_float4(0.f, 0.f, 0.f, 0.f); vb = va;
        if (tn < A_NT) {
            const int grow = tn * A_TILE + r;
            if (grow < NNODE) {
                const float4* zr = reinterpret_cast<const float4*>(z + (size_t)grow * 64 + cq);
                va = zr[0]; vb = zr[1];
            }
        }

        float acc[18][4];
        #pragma unroll
        for (int n = 0; n < 18; n++)
            #pragma unroll
            for (int q = 0; q < 4; q++) acc[n][q] = 0.0f;

        #pragma unroll
        for (int k = 0; k < 4; k++) {
            uint32_t ah[4], al[4];
            const uint32_t arow = (uint32_t)(mi * 16 + (lane & 15)) * A_ZSTR
                                + (uint32_t)k * 32 + ((lane >> 4) << 4);
            ldm_x4(ah, sb + A_ZH + arow);
            ldm_x4(al, sb + A_ZL + arow);
            const uint32_t brow = (uint32_t)(k * 16 + (lane & 15)) * A_WSTR + (uint32_t)ni * 288;
            #pragma unroll
            for (int n = 0; n < 18; n++) {
                uint32_t bh[2], bl[2];
                ldm_x2t(bh, sb + A_WH + brow + n * 16);
                ldm_x2t(bl, sb + A_WL + brow + n * 16);
                mma_bf16(acc[n], ah, bh);
                mma_bf16(acc[n], al, bh);
                mma_bf16(acc[n], ah, bl);
            }
        }

        const int r0 = t * A_TILE + mi * 16 + (lane >> 2);
        const int r1 = r0 + 8;
        #pragma unroll
        for (int n = 0; n < 18; n++) {
            const int j = ni * 144 + n * 8 + 2 * (lane & 3);
            if (r0 < NNODE) {
                float2 o; o.x = acc[n][0]; o.y = acc[n][1];
                *reinterpret_cast<float2*>(scratch_ptr(r0, j)) = o;
            }
            if (r1 < NNODE) {
                float2 o; o.x = acc[n][2]; o.y = acc[n][3];
                *reinterpret_cast<float2*>(scratch_ptr(r1, j)) = o;
            }
        }
    }
}

// =====================================================================
// Kernel F (fused, dst-sorted, prefetched, __ldg gathers)
// =====================================================================
__global__ __launch_bounds__(F_THR, 3)
void edge_gate_kernel(const float* __restrict__ ea,
                      const float* __restrict__ Wffw,
                      const float* __restrict__ bias,
                      const float* __restrict__ bf,
                      const float* __restrict__ bs,
                      float* __restrict__ z_edge,
                      float* __restrict__ z_node)
{
    extern __shared__ char sm[];
    const uint32_t sb = smem_u32(sm);
    const int tid = threadIdx.x, wid = tid >> 5, lane = tid & 31;
    const int mi = wid >> 2, ni = wid & 3;

    // ---- one-time init ----
    for (int idx = tid; idx < 32 * 160; idx += F_THR) {
        const int k = idx / 160, n = idx - k * 160;
        const float w = Wffw[(128 + k) * 160 + n];
        const __nv_bfloat16 h = __float2bfloat16(w);
        const __nv_bfloat16 l = __float2bfloat16(w - __bfloat162float(h));
        *reinterpret_cast<__nv_bfloat16*>(sm + F_WH + k * F_WSTR + n * 2) = h;
        *reinterpret_cast<__nv_bfloat16*>(sm + F_WL + k * F_WSTR + n * 2) = l;
    }
    if (tid < 160) reinterpret_cast<float*>(sm + F_BIAS)[tid] = bias[tid];
    for (int i = tid; i < 512; i += F_THR) {
        const float x0 = -10.0f + (float)i * (20.0f / 512.0f);
        const float x1 = x0 + (20.0f / 512.0f);
        const float s0 = 1.0f / (1.0f + expf(-x0));
        const float s1 = 1.0f / (1.0f + expf(-x1));
        const float ds = s1 - s0;
        reinterpret_cast<float2*>(sm + F_LSIG)[i] = make_float2(s0 - (float)i * ds, ds);
        const float p0 = fmaxf(x0, 0.0f) + log1pf(expf(-fabsf(x0)));
        const float p1 = fmaxf(x1, 0.0f) + log1pf(expf(-fabsf(x1)));
        const float dp = p1 - p0;
        reinterpret_cast<float2*>(sm + F_LSP)[i] = make_float2(p0 - (float)i * dp, dp);
    }
    if (tid < 64) {
        reinterpret_cast<float*>(sm + F_BF)[tid] = bf[tid];
        reinterpret_cast<float*>(sm + F_BS)[tid] = bs[tid];
    }

    const float*  s_bias = reinterpret_cast<const float*>(sm + F_BIAS);
    const float2* t_sig  = reinterpret_cast<const float2*>(sm + F_LSIG);
    const float2* t_sp   = reinterpret_cast<const float2*>(sm + F_LSP);
    const float*  s_bf   = reinterpret_cast<const float*>(sm + F_BF);
    const float*  s_bs   = reinterpret_cast<const float*>(sm + F_BS);

    const int e_q = tid >> 2, q = tid & 3;
    const int e_o = tid >> 3, oct = tid & 7;

    // ---- prefetch first tile's perm + ea ----
    float4 pa = make_float4(0.f, 0.f, 0.f, 0.f), pb = pa;
    int pe_cur = 0;
    int t = blockIdx.x;
    if (t < F_NT) {
        pe_cur = __ldg(&g_perm[t * F_TILE + e_q]);
        const float4* ep = reinterpret_cast<const float4*>(ea + (size_t)pe_cur * 32) + q * 2;
        pa = __ldcs(ep);
        pb = __ldcs(ep + 1);
    }

    for (; t < F_NT; t += gridDim.x) {
        __syncthreads();

        // ---- phase 1: STS prefetched ea tile ----
        {
            uint32_t* xh = reinterpret_cast<uint32_t*>(sm + F_EH + e_q * F_ESTR + q * 16);
            uint32_t* xl = reinterpret_cast<uint32_t*>(sm + F_EL + e_q * F_ESTR + q * 16);
            uint32_t h0, l0, h1, l1;
            split2(pa.x, pa.y, h0, l0); split2(pa.z, pa.w, h1, l1);
            xh[0] = h0; xh[1] = h1; xl[0] = l0; xl[1] = l1;
            split2(pb.x, pb.y, h0, l0); split2(pb.z, pb.w, h1, l1);
            xh[2] = h0; xh[3] = h1; xl[2] = l0; xl[3] = l1;
        }
        __syncthreads();

        // ---- prefetch next tile during GEMM ----
        const int tn = t + gridDim.x;
        if (tn < F_NT) {
            const int pe = __ldg(&g_perm[tn * F_TILE + e_q]);
            const float4* ep = reinterpret_cast<const float4*>(ea + (size_t)pe * 32) + q * 2;
            pa = __ldcs(ep);
            pb = __ldcs(ep + 1);
        }

        // ---- phase 2: GEMM ea@W3 (K=32) ----
        float acc[2][5][4];
        #pragma unroll
        for (int m = 0; m < 2; m++)
            #pragma unroll
            for (int n = 0; n < 5; n++)
                #pragma unroll
                for (int r = 0; r < 4; r++) acc[m][n][r] = 0.0f;

        #pragma unroll
        for (int k = 0; k < 2; k++) {
            uint32_t ah[2][4], al[2][4];
            const uint32_t arow = (uint32_t)(mi * 32 + (lane & 15)) * F_ESTR
                                + (uint32_t)k * 32 + ((lane >> 4) << 4);
            #pragma unroll
            for (int m = 0; m < 2; m++) {
                ldm_x4(ah[m], sb + F_EH + arow + m * 16 * F_ESTR);
                ldm_x4(al[m], sb + F_EL + arow + m * 16 * F_ESTR);
            }
            const uint32_t brow = (uint32_t)(k * 16 + (lane & 15)) * F_WSTR + (uint32_t)ni * 80;
            #pragma unroll
            for (int n = 0; n < 5; n++) {
                uint32_t bh[2], bl[2];
                ldm_x2t(bh, sb + F_WH + brow + n * 16);
                ldm_x2t(bl, sb + F_WL + brow + n * 16);
                #pragma unroll
                for (int m = 0; m < 2; m++) {
                    mma_bf16(acc[m][n], ah[m], bh);
                    mma_bf16(acc[m][n], al[m], bh);
                    mma_bf16(acc[m][n], ah[m], bl);
                }
            }
        }
        __syncthreads();

        // ---- phase 3a: stage acc -> D tile (smem) ----
        {
            float* D = reinterpret_cast<float*>(sm + F_UNI);
            #pragma unroll
            for (int m = 0; m < 2; m++) {
                const int row = mi * 32 + m * 16 + (lane >> 2);
                #pragma unroll
                for (int n = 0; n < 5; n++) {
                    const int j = ni * 40 + n * 8 + 2 * (lane & 3);
                    float2 o0, o1;
                    o0.x = acc[m][n][0]; o0.y = acc[m][n][1];
                    o1.x = acc[m][n][2]; o1.y = acc[m][n][3];
                    *reinterpret_cast<float2*>(D + row * F_DSTR + j) = o0;
                    *reinterpret_cast<float2*>(D + (row + 8) * F_DSTR + j) = o1;
                }
            }
        }
        __syncthreads();

        // ---- phase 3b + 4: coalesced epilogues, __ldg gathers ----
        #pragma unroll
        for (int eh = 0; eh < 2; eh++) {
            const int le = e_o + 32 * eh;
            const int si = t * F_TILE + le;
            const int pe = __ldg(&g_perm[si]);
            const int s  = __ldg(&g_esrc[si]);
            const int d  = __ldg(&g_edst[si]);

            const float4* U = reinterpret_cast<const float4*>(g_UV + (size_t)s * 320);
            const float4* V = reinterpret_cast<const float4*>(g_UV + (size_t)d * 320 + 160);
            const float4* Pf = reinterpret_cast<const float4*>(g_G1 + (size_t)d * 128);
            const float4* Qf = reinterpret_cast<const float4*>(g_G2 + (size_t)s * 128);
            const float4* D = reinterpret_cast<const float4*>(sm + F_UNI) + le * (F_DSTR / 4);
            const float4* B = reinterpret_cast<const float4*>(s_bias);
            float4* O = reinterpret_cast<float4*>(z_edge + (size_t)pe * 160);

            // front-batch all gathers (read-only path allows overlap with stores)
            float4 u[5], v[5], pf[2], qf[2], ps[2], qs[2];
            #pragma unroll
            for (int i = 0; i < 5; i++) u[i] = __ldg(&U[oct + 8 * i]);
            #pragma unroll
            for (int i = 0; i < 5; i++) v[i] = __ldg(&V[oct + 8 * i]);
            #pragma unroll
            for (int i = 0; i < 2; i++) pf[i] = __ldg(&Pf[oct + 8 * i]);
            #pragma unroll
            for (int i = 0; i < 2; i++) qf[i] = __ldg(&Qf[oct + 8 * i]);
            #pragma unroll
            for (int i = 0; i < 2; i++) ps[i] = __ldg(&Pf[16 + oct + 8 * i]);
            #pragma unroll
            for (int i = 0; i < 2; i++) qs[i] = __ldg(&Qf[16 + oct + 8 * i]);

            #pragma unroll
            for (int i = 0; i < 5; i++) {
                const int c4 = oct + 8 * i;
                const float4 dd = D[c4], bb = B[c4];
                float4 o;
                o.x = fmaxf(dd.x + u[i].x + v[i].x + bb.x, 0.0f);
                o.y = fmaxf(dd.y + u[i].y + v[i].y + bb.y, 0.0f);
                o.z = fmaxf(dd.z + u[i].z + v[i].z + bb.z, 0.0f);
                o.w = fmaxf(dd.w + u[i].w + v[i].w + bb.w, 0.0f);
                __stcs(&O[c4], o);
            }

            const float4* Bf = reinterpret_cast<const float4*>(s_bf);
            const float4* Bs = reinterpret_cast<const float4*>(s_bs);
            float4* out = reinterpret_cast<float4*>(z_node + (size_t)d * 64);

            #pragma unroll
            for (int i = 0; i < 2; i++) {
                const int c4 = oct + 8 * i;
                const float4 bfv = Bf[c4], bsv = Bs[c4];
                float4 msg;
                {
                    const float f = pf[i].x + qf[i].x + bfv.x;
                    const float vv = ps[i].x + qs[i].x + bsv.x;
                    msg.x = lut_eval(t_sig, f) * fmaxf(lut_eval(t_sp, vv), vv);
                }
                {
                    const float f = pf[i].y + qf[i].y + bfv.y;
                    const float vv = ps[i].y + qs[i].y + bsv.y;
                    msg.y = lut_eval(t_sig, f) * fmaxf(lut_eval(t_sp, vv), vv);
                }
                {
                    const float f = pf[i].z + qf[i].z + bfv.z;
                    const float vv = ps[i].z + qs[i].z + bsv.z;
                    msg.z = lut_eval(t_sig, f) * fmaxf(lut_eval(t_sp, vv), vv);
                }
                {
                    const float f = pf[i].w + qf[i].w + bfv.w;
                    const float vv = ps[i].w + qs[i].w + bsv.w;
                    msg.w = lut_eval(t_sig, f) * fmaxf(lut_eval(t_sp, vv), vv);
                }
                atomicAdd(&out[c4], msg);
            }
        }
    }
}

extern "C" void kernel_launch(void* const* d_in, const int* in_sizes, int n_in,
                              void* d_out, int out_size)
{
    const float* z    = (const float*)d_in[0];
    const float* ea   = (const float*)d_in[1];
    const int*   eidx = (const int*)  d_in[2];
    const float* Wffw = (const float*)d_in[3];
    const float* bffw = (const float*)d_in[4];
    const float* Wf   = (const float*)d_in[5];
    const float* bf   = (const float*)d_in[6];
    const float* Ws   = (const float*)d_in[7];
    const float* bs   = (const float*)d_in[8];

    float* z_node = (float*)d_out;
    float* z_edge = (float*)d_out + (size_t)NNODE * 64;
    const int* srcp = eidx;
    const int* dstp = eidx + NE;

    static bool init = false;
    if (!init) {
        init = true;
        cudaFuncSetAttribute(node_gemm_kernel, cudaFuncAttributeMaxDynamicSharedMemorySize, A_SMEM);
        cudaFuncSetAttribute(edge_gate_kernel, cudaFuncAttributeMaxDynamicSharedMemorySize, F_SMEM);
    }

    // residual base for scatter-add
    cudaMemcpyAsync(z_node, z, (size_t)NNODE * 64 * sizeof(float),
                    cudaMemcpyDeviceToDevice, 0);

    // counting sort of edges by dst
    sort_zero_kernel<<<(NNODE + 255) / 256, 256>>>();
    sort_hist_kernel<<<(NE + 255) / 256, 256>>>(dstp);
    sort_scan_kernel<<<1, 1024>>>();
    sort_scatter_kernel<<<(NE + 255) / 256, 256>>>(srcp, dstp);

    node_gemm_kernel<<<148, A_THR, A_SMEM, 0>>>(z, Wffw, Wf, Ws);
    edge_gate_kernel<<<444, F_THR, F_SMEM, 0>>>(ea, Wffw, bffw, bf, bs, z_edge, z_node);
}

// round 17
// speedup vs baseline: 1.5426x; 1.5426x over previous
#include <cuda_runtime.h>
#include <cuda_bf16.h>
#include <cstdint>
#include <math.h>

#define NE      800000
#define NNODE   50000

// ---------------- scratch (static device arrays; no allocation) ----------------
__device__ float g_UV[(size_t)NNODE * 320];   // [n][0:160]=U=z@W1, [160:320]=V=z@W2
__device__ float g_G1[(size_t)NNODE * 128];   // [n][0:64]=P, [64:128]=R
__device__ float g_G2[(size_t)NNODE * 128];   // [n][0:64]=Q, [64:128]=S
__device__ int   g_cnt[NNODE];
__device__ int   g_off[NNODE];
__device__ int   g_perm[NE];
__device__ int   g_esrc[NE];
__device__ int   g_edst[NE];

// ---------------- kernel A (node GEMM, persistent) ----------------
#define A_THR  512
#define A_TILE 64
#define A_NT   ((NNODE + A_TILE - 1) / A_TILE)
#define A_ZSTR 144
#define A_WSTR 1168
#define A_ZH   0
#define A_ZL   (A_ZH + 64 * A_ZSTR)
#define A_WH   (A_ZL + 64 * A_ZSTR)
#define A_WL   (A_WH + 64 * A_WSTR)
#define A_SMEM (A_WL + 64 * A_WSTR)              // 167936

// ---------------- kernel F ----------------
#define F_THR   256
#define F_TILE  64
#define F_NT    (NE / F_TILE)                    // 12500
#define F_ESTR  80
#define F_WSTR  336
#define F_DSTR  168
#define F_WH    0
#define F_WL    (F_WH + 32 * F_WSTR)
#define F_BIAS  (F_WL + 32 * F_WSTR)
#define F_LSIG  (F_BIAS + 640)
#define F_LSP   (F_LSIG + 4096)
#define F_BF    (F_LSP + 4096)
#define F_BS    (F_BF + 256)
#define F_UNI   (F_BS + 256)
#define F_EH    (F_UNI)
#define F_EL    (F_UNI + 64 * F_ESTR)
#define F_SMEM  (F_UNI + 64 * F_DSTR * 4)        // 73856 -> 3 CTAs/SM

static __device__ __forceinline__ uint32_t smem_u32(const void* p) {
    uint32_t a;
    asm("{ .reg .u64 t; cvta.to.shared.u64 t, %1; cvt.u32.u64 %0, t; }" : "=r"(a) : "l"(p));
    return a;
}
static __device__ __forceinline__ void ldm_x4(uint32_t* r, uint32_t addr) {
    asm volatile("ldmatrix.sync.aligned.m8n8.x4.shared.b16 {%0,%1,%2,%3}, [%4];"
                 : "=r"(r[0]), "=r"(r[1]), "=r"(r[2]), "=r"(r[3]) : "r"(addr));
}
static __device__ __forceinline__ void ldm_x2t(uint32_t* r, uint32_t addr) {
    asm volatile("ldmatrix.sync.aligned.m8n8.x2.trans.shared.b16 {%0,%1}, [%2];"
                 : "=r"(r[0]), "=r"(r[1]) : "r"(addr));
}
static __device__ __forceinline__ void mma_bf16(float* c, const uint32_t* a, const uint32_t* b) {
    asm volatile("mma.sync.aligned.m16n8k16.row.col.f32.bf16.bf16.f32 "
                 "{%0,%1,%2,%3}, {%4,%5,%6,%7}, {%8,%9}, {%0,%1,%2,%3};"
                 : "+f"(c[0]), "+f"(c[1]), "+f"(c[2]), "+f"(c[3])
                 : "r"(a[0]), "r"(a[1]), "r"(a[2]), "r"(a[3]), "r"(b[0]), "r"(b[1]));
}
static __device__ __forceinline__ void split2(float x0, float x1, uint32_t& hi, uint32_t& lo) {
    uint32_t h;
    asm("cvt.rn.bf16x2.f32 %0, %1, %2;" : "=r"(h) : "f"(x1), "f"(x0));
    float h0 = __uint_as_float(h << 16);
    float h1 = __uint_as_float(h & 0xFFFF0000u);
    uint32_t l;
    asm("cvt.rn.bf16x2.f32 %0, %1, %2;" : "=r"(l) : "f"(x1 - h1), "f"(x0 - h0));
    hi = h; lo = l;
}
static __device__ __forceinline__ float* scratch_ptr(int row, int j) {
    if (j < 320) return g_UV + (size_t)row * 320 + j;
    if (j < 448) return g_G1 + (size_t)row * 128 + (j - 320);
    return g_G2 + (size_t)row * 128 + (j - 448);
}
static __device__ __forceinline__ float lut_eval(const float2* tab, float x) {
    float tp = fmaf(x, 512.0f / 20.0f, 256.0f);
    tp = fminf(fmaxf(tp, 0.0f), 511.5f);
    const float2 c = tab[(int)tp];
    return fmaf(tp, c.y, c.x);
}

// =====================================================================
// Sort kernels: counting sort of edges by dst
// =====================================================================
__global__ void sort_zero_kernel() {
    const int i = blockIdx.x * 256 + threadIdx.x;
    if (i < NNODE) g_cnt[i] = 0;
}
__global__ void sort_hist_kernel(const int* __restrict__ dstp) {
    const int e = blockIdx.x * 256 + threadIdx.x;
    if (e < NE) atomicAdd(&g_cnt[dstp[e]], 1);
}
__global__ __launch_bounds__(1024) void sort_scan_kernel() {
    __shared__ int part[1024];
    const int tid = threadIdx.x;
    const int CH = (NNODE + 1023) / 1024;
    const int base = tid * CH;
    int sum = 0;
    for (int i = 0; i < CH; i++) {
        const int idx = base + i;
        if (idx < NNODE) sum += g_cnt[idx];
    }
    part[tid] = sum;
    __syncthreads();
    for (int d = 1; d < 1024; d <<= 1) {
        const int v = (tid >= d) ? part[tid - d] : 0;
        __syncthreads();
        part[tid] += v;
        __syncthreads();
    }
    int run = (tid == 0) ? 0 : part[tid - 1];
    for (int i = 0; i < CH; i++) {
        const int idx = base + i;
        if (idx < NNODE) {
            g_off[idx] = run;
            run += g_cnt[idx];
        }
    }
}
__global__ void sort_scatter_kernel(const int* __restrict__ srcp,
                                    const int* __restrict__ dstp) {
    const int e = blockIdx.x * 256 + threadIdx.x;
    if (e < NE) {
        const int d = dstp[e];
        const int pos = atomicAdd(&g_off[d], 1);
        g_perm[pos] = e;
        g_esrc[pos] = srcp[e];
        g_edst[pos] = d;
    }
}

// =====================================================================
// Kernel A (persistent): [NNODE,64] @ BigW[64,576] -> UV | G1 | G2
// =====================================================================
__global__ __launch_bounds__(A_THR, 1)
void node_gemm_kernel(const float* __restrict__ z,
                      const float* __restrict__ Wffw,
                      const float* __restrict__ Wf,
                      const float* __restrict__ Ws)
{
    extern __shared__ char sm[];
    const uint32_t sb = smem_u32(sm);
    const int tid = threadIdx.x, wid = tid >> 5, lane = tid & 31;
    const int mi = wid >> 2, ni = wid & 3;

    for (int idx = tid; idx < 64 * 576; idx += A_THR) {
        const int k = idx / 576, j = idx - k * 576;
        float w;
        if (j < 160)      w = Wffw[k * 160 + j];
        else if (j < 320) w = Wffw[(64 + k) * 160 + (j - 160)];
        else if (j < 384) w = Wf[k * 64 + (j - 320)];
        else if (j < 448) w = Ws[k * 64 + (j - 384)];
        else if (j < 512) w = Wf[(64 + k) * 64 + (j - 448)];
        else              w = Ws[(64 + k) * 64 + (j - 512)];
        const __nv_bfloat16 h = __float2bfloat16(w);
        const __nv_bfloat16 l = __float2bfloat16(w - __bfloat162float(h));
        *reinterpret_cast<__nv_bfloat16*>(sm + A_WH + k * A_WSTR + j * 2) = h;
        *reinterpret_cast<__nv_bfloat16*>(sm + A_WL + k * A_WSTR + j * 2) = l;
    }

    const int r = tid >> 3, cq = (tid & 7) * 8;

    float4 va = make_float4(0.f, 0.f, 0.f, 0.f), vb = va;
    int t = blockIdx.x;
    if (t < A_NT) {
        const int grow = t * A_TILE + r;
        if (grow < NNODE) {
            const float4* zr = reinterpret_cast<const float4*>(z + (size_t)grow * 64 + cq);
            va = zr[0]; vb = zr[1];
        }
    }

    for (; t < A_NT; t += gridDim.x) {
        __syncthreads();

        {
            uint32_t* zh = reinterpret_cast<uint32_t*>(sm + A_ZH + r * A_ZSTR + cq * 2);
            uint32_t* zl = reinterpret_cast<uint32_t*>(sm + A_ZL + r * A_ZSTR + cq * 2);
            uint32_t h0, l0, h1, l1;
            split2(va.x, va.y, h0, l0); split2(va.z, va.w, h1, l1);
            zh[0] = h0; zh[1] = h1; zl[0] = l0; zl[1] = l1;
            split2(vb.x, vb.y, h0, l0); split2(vb.z, vb.w, h1, l1);
            zh[2] = h0; zh[3] = h1; zl[2] = l0; zl[3] = l1;
        }
        __syncthreads();

        const int tn = t + gridDim.x;
        va = make_float4(0.f, 0.f, 0.f, 0.f); vb = va;
        if (tn < A_NT) {
            const int grow = tn * A_TILE + r;
            if (grow < NNODE) {
                const float4* zr = reinterpret_cast<const float4*>(z + (size_t)grow * 64 + cq);
                va = zr[0]; vb = zr[1];
            }
        }

        float acc[18][4];
        #pragma unroll
        for (int n = 0; n < 18; n++)
            #pragma unroll
            for (int q = 0; q < 4; q++) acc[n][q] = 0.0f;

        #pragma unroll
        for (int k = 0; k < 4; k++) {
            uint32_t ah[4], al[4];
            const uint32_t arow = (uint32_t)(mi * 16 + (lane & 15)) * A_ZSTR
                                + (uint32_t)k * 32 + ((lane >> 4) << 4);
            ldm_x4(ah, sb + A_ZH + arow);
            ldm_x4(al, sb + A_ZL + arow);
            const uint32_t brow = (uint32_t)(k * 16 + (lane & 15)) * A_WSTR + (uint32_t)ni * 288;
            #pragma unroll
            for (int n = 0; n < 18; n++) {
                uint32_t bh[2], bl[2];
                ldm_x2t(bh, sb + A_WH + brow + n * 16);
                ldm_x2t(bl, sb + A_WL + brow + n * 16);
                mma_bf16(acc[n], ah, bh);
                mma_bf16(acc[n], al, bh);
                mma_bf16(acc[n], ah, bl);
            }
        }

        const int r0 = t * A_TILE + mi * 16 + (lane >> 2);
        const int r1 = r0 + 8;
        #pragma unroll
        for (int n = 0; n < 18; n++) {
            const int j = ni * 144 + n * 8 + 2 * (lane & 3);
            if (r0 < NNODE) {
                float2 o; o.x = acc[n][0]; o.y = acc[n][1];
                *reinterpret_cast<float2*>(scratch_ptr(r0, j)) = o;
            }
            if (r1 < NNODE) {
                float2 o; o.x = acc[n][2]; o.y = acc[n][3];
                *reinterpret_cast<float2*>(scratch_ptr(r1, j)) = o;
            }
        }
    }
}

// =====================================================================
// Kernel F (fused, dst-sorted edge order) — round-14 version
// =====================================================================
__global__ __launch_bounds__(F_THR, 3)
void edge_gate_kernel(const float* __restrict__ ea,
                      const float* __restrict__ Wffw,
                      const float* __restrict__ bias,
                      const float* __restrict__ bf,
                      const float* __restrict__ bs,
                      float* __restrict__ z_edge,
                      float* __restrict__ z_node)
{
    extern __shared__ char sm[];
    const uint32_t sb = smem_u32(sm);
    const int tid = threadIdx.x, wid = tid >> 5, lane = tid & 31;
    const int mi = wid >> 2, ni = wid & 3;

    // ---- one-time init ----
    for (int idx = tid; idx < 32 * 160; idx += F_THR) {
        const int k = idx / 160, n = idx - k * 160;
        const float w = Wffw[(128 + k) * 160 + n];
        const __nv_bfloat16 h = __float2bfloat16(w);
        const __nv_bfloat16 l = __float2bfloat16(w - __bfloat162float(h));
        *reinterpret_cast<__nv_bfloat16*>(sm + F_WH + k * F_WSTR + n * 2) = h;
        *reinterpret_cast<__nv_bfloat16*>(sm + F_WL + k * F_WSTR + n * 2) = l;
    }
    if (tid < 160) reinterpret_cast<float*>(sm + F_BIAS)[tid] = bias[tid];
    for (int i = tid; i < 512; i += F_THR) {
        const float x0 = -10.0f + (float)i * (20.0f / 512.0f);
        const float x1 = x0 + (20.0f / 512.0f);
        const float s0 = 1.0f / (1.0f + expf(-x0));
        const float s1 = 1.0f / (1.0f + expf(-x1));
        const float ds = s1 - s0;
        reinterpret_cast<float2*>(sm + F_LSIG)[i] = make_float2(s0 - (float)i * ds, ds);
        const float p0 = fmaxf(x0, 0.0f) + log1pf(expf(-fabsf(x0)));
        const float p1 = fmaxf(x1, 0.0f) + log1pf(expf(-fabsf(x1)));
        const float dp = p1 - p0;
        reinterpret_cast<float2*>(sm + F_LSP)[i] = make_float2(p0 - (float)i * dp, dp);
    }
    if (tid < 64) {
        reinterpret_cast<float*>(sm + F_BF)[tid] = bf[tid];
        reinterpret_cast<float*>(sm + F_BS)[tid] = bs[tid];
    }

    const float*  s_bias = reinterpret_cast<const float*>(sm + F_BIAS);
    const float2* t_sig  = reinterpret_cast<const float2*>(sm + F_LSIG);
    const float2* t_sp   = reinterpret_cast<const float2*>(sm + F_LSP);
    const float*  s_bf   = reinterpret_cast<const float*>(sm + F_BF);
    const float*  s_bs   = reinterpret_cast<const float*>(sm + F_BS);

    const int e_q = tid >> 2, q = tid & 3;
    const int e_o = tid >> 3, oct = tid & 7;

    for (int t = blockIdx.x; t < F_NT; t += gridDim.x) {
        __syncthreads();

        // ---- phase 1: ea tile (via perm) -> smem ----
        {
            const int pe = g_perm[t * F_TILE + e_q];
            const float4* ep = reinterpret_cast<const float4*>(ea + (size_t)pe * 32) + q * 2;
            const float4 a = __ldcs(ep);
            const float4 b = __ldcs(ep + 1);
            uint32_t* xh = reinterpret_cast<uint32_t*>(sm + F_EH + e_q * F_ESTR + q * 16);
            uint32_t* xl = reinterpret_cast<uint32_t*>(sm + F_EL + e_q * F_ESTR + q * 16);
            uint32_t h0, l0, h1, l1;
            split2(a.x, a.y, h0, l0); split2(a.z, a.w, h1, l1);
            xh[0] = h0; xh[1] = h1; xl[0] = l0; xl[1] = l1;
            split2(b.x, b.y, h0, l0); split2(b.z, b.w, h1, l1);
            xh[2] = h0; xh[3] = h1; xl[2] = l0; xl[3] = l1;
        }
        __syncthreads();

        // ---- phase 2: GEMM ea@W3 (K=32) ----
        float acc[2][5][4];
        #pragma unroll
        for (int m = 0; m < 2; m++)
            #pragma unroll
            for (int n = 0; n < 5; n++)
                #pragma unroll
                for (int r = 0; r < 4; r++) acc[m][n][r] = 0.0f;

        #pragma unroll
        for (int k = 0; k < 2; k++) {
            uint32_t ah[2][4], al[2][4];
            const uint32_t arow = (uint32_t)(mi * 32 + (lane & 15)) * F_ESTR
                                + (uint32_t)k * 32 + ((lane >> 4) << 4);
            #pragma unroll
            for (int m = 0; m < 2; m++) {
                ldm_x4(ah[m], sb + F_EH + arow + m * 16 * F_ESTR);
                ldm_x4(al[m], sb + F_EL + arow + m * 16 * F_ESTR);
            }
            const uint32_t brow = (uint32_t)(k * 16 + (lane & 15)) * F_WSTR + (uint32_t)ni * 80;
            #pragma unroll
            for (int n = 0; n < 5; n++) {
                uint32_t bh[2], bl[2];
                ldm_x2t(bh, sb + F_WH + brow + n * 16);
                ldm_x2t(bl, sb + F_WL + brow + n * 16);
                #pragma unroll
                for (int m = 0; m < 2; m++) {
                    mma_bf16(acc[m][n], ah[m], bh);
                    mma_bf16(acc[m][n], al[m], bh);
                    mma_bf16(acc[m][n], ah[m], bl);
                }
            }
        }
        __syncthreads();

        // ---- phase 3a: stage acc -> D tile (smem) ----
        {
            float* D = reinterpret_cast<float*>(sm + F_UNI);
            #pragma unroll
            for (int m = 0; m < 2; m++) {
                const int row = mi * 32 + m * 16 + (lane >> 2);
                #pragma unroll
                for (int n = 0; n < 5; n++) {
                    const int j = ni * 40 + n * 8 + 2 * (lane & 3);
                    float2 o0, o1;
                    o0.x = acc[m][n][0]; o0.y = acc[m][n][1];
                    o1.x = acc[m][n][2]; o1.y = acc[m][n][3];
                    *reinterpret_cast<float2*>(D + row * F_DSTR + j) = o0;
                    *reinterpret_cast<float2*>(D + (row + 8) * F_DSTR + j) = o1;
                }
            }
        }
        __syncthreads();

        // ---- phase 3b + 4: coalesced epilogues over sorted edges ----
        #pragma unroll
        for (int eh = 0; eh < 2; eh++) {
            const int le = e_o + 32 * eh;
            const int si = t * F_TILE + le;
            const int pe = g_perm[si];
            const int s  = g_esrc[si];
            const int d  = g_edst[si];

            const float4* U = reinterpret_cast<const float4*>(g_UV + (size_t)s * 320);
            const float4* V = reinterpret_cast<const float4*>(g_UV + (size_t)d * 320 + 160);
            const float4* D = reinterpret_cast<const float4*>(sm + F_UNI) + le * (F_DSTR / 4);
            const float4* B = reinterpret_cast<const float4*>(s_bias);
            float4* O = reinterpret_cast<float4*>(z_edge + (size_t)pe * 160);

            float4 u[5], v[5];
            #pragma unroll
            for (int i = 0; i < 5; i++) u[i] = U[oct + 8 * i];
            #pragma unroll
            for (int i = 0; i < 5; i++) v[i] = V[oct + 8 * i];
            #pragma unroll
            for (int i = 0; i < 5; i++) {
                const int c4 = oct + 8 * i;
                const float4 dd = D[c4], bb = B[c4];
                float4 o;
                o.x = fmaxf(dd.x + u[i].x + v[i].x + bb.x, 0.0f);
                o.y = fmaxf(dd.y + u[i].y + v[i].y + bb.y, 0.0f);
                o.z = fmaxf(dd.z + u[i].z + v[i].z + bb.z, 0.0f);
                o.w = fmaxf(dd.w + u[i].w + v[i].w + bb.w, 0.0f);
                __stcs(&O[c4], o);
            }

            const float4* Pf = reinterpret_cast<const float4*>(g_G1 + (size_t)d * 128);
            const float4* Qf = reinterpret_cast<const float4*>(g_G2 + (size_t)s * 128);
            const float4* Ps = Pf + 16;
            const float4* Qs = Qf + 16;
            const float4* Bf = reinterpret_cast<const float4*>(s_bf);
            const float4* Bs = reinterpret_cast<const float4*>(s_bs);
            float4* out = reinterpret_cast<float4*>(z_node + (size_t)d * 64);

            float4 pf[2], qf[2], ps[2], qs[2];
            #pragma unroll
            for (int i = 0; i < 2; i++) pf[i] = Pf[oct + 8 * i];
            #pragma unroll
            for (int i = 0; i < 2; i++) qf[i] = Qf[oct + 8 * i];
            #pragma unroll
            for (int i = 0; i < 2; i++) ps[i] = Ps[oct + 8 * i];
            #pragma unroll
            for (int i = 0; i < 2; i++) qs[i] = Qs[oct + 8 * i];

            #pragma unroll
            for (int i = 0; i < 2; i++) {
                const int c4 = oct + 8 * i;
                const float4 bfv = Bf[c4], bsv = Bs[c4];
                float4 msg;
                {
                    const float f = pf[i].x + qf[i].x + bfv.x;
                    const float vv = ps[i].x + qs[i].x + bsv.x;
                    msg.x = lut_eval(t_sig, f) * fmaxf(lut_eval(t_sp, vv), vv);
                }
                {
                    const float f = pf[i].y + qf[i].y + bfv.y;
                    const float vv = ps[i].y + qs[i].y + bsv.y;
                    msg.y = lut_eval(t_sig, f) * fmaxf(lut_eval(t_sp, vv), vv);
                }
                {
                    const float f = pf[i].z + qf[i].z + bfv.z;
                    const float vv = ps[i].z + qs[i].z + bsv.z;
                    msg.z = lut_eval(t_sig, f) * fmaxf(lut_eval(t_sp, vv), vv);
                }
                {
                    const float f = pf[i].w + qf[i].w + bfv.w;
                    const float vv = ps[i].w + qs[i].w + bsv.w;
                    msg.w = lut_eval(t_sig, f) * fmaxf(lut_eval(t_sp, vv), vv);
                }
                atomicAdd(&out[c4], msg);
            }
        }
    }
}

extern "C" void kernel_launch(void* const* d_in, const int* in_sizes, int n_in,
                              void* d_out, int out_size)
{
    const float* z    = (const float*)d_in[0];
    const float* ea   = (const float*)d_in[1];
    const int*   eidx = (const int*)  d_in[2];
    const float* Wffw = (const float*)d_in[3];
    const float* bffw = (const float*)d_in[4];
    const float* Wf   = (const float*)d_in[5];
    const float* bf   = (const float*)d_in[6];
    const float* Ws   = (const float*)d_in[7];
    const float* bs   = (const float*)d_in[8];

    float* z_node = (float*)d_out;
    float* z_edge = (float*)d_out + (size_t)NNODE * 64;
    const int* srcp = eidx;
    const int* dstp = eidx + NE;

    static cudaStream_t s2 = nullptr;
    static cudaEvent_t evFork = nullptr, evSort = nullptr;
    if (s2 == nullptr) {
        cudaStreamCreateWithFlags(&s2, cudaStreamNonBlocking);
        cudaEventCreateWithFlags(&evFork, cudaEventDisableTiming);
        cudaEventCreateWithFlags(&evSort, cudaEventDisableTiming);
        cudaFuncSetAttribute(node_gemm_kernel, cudaFuncAttributeMaxDynamicSharedMemorySize, A_SMEM);
        cudaFuncSetAttribute(edge_gate_kernel, cudaFuncAttributeMaxDynamicSharedMemorySize, F_SMEM);
    }

    // fork side stream FROM the capturing stream (capture-legal)
    cudaEventRecord(evFork, 0);
    cudaStreamWaitEvent(s2, evFork, 0);

    // side stream: counting sort of edges by dst (concurrent with A)
    sort_zero_kernel<<<(NNODE + 255) / 256, 256, 0, s2>>>();
    sort_hist_kernel<<<(NE + 255) / 256, 256, 0, s2>>>(dstp);
    sort_scan_kernel<<<1, 1024, 0, s2>>>();
    sort_scatter_kernel<<<(NE + 255) / 256, 256, 0, s2>>>(srcp, dstp);
    cudaEventRecord(evSort, s2);

    // stream 0: residual memcpy -> node GEMM (concurrent with sort)
    cudaMemcpyAsync(z_node, z, (size_t)NNODE * 64 * sizeof(float),
                    cudaMemcpyDeviceToDevice, 0);
    node_gemm_kernel<<<148, A_THR, A_SMEM, 0>>>(z, Wffw, Wf, Ws);

    // join: F needs both the sort results and A's scratch
    cudaStreamWaitEvent(0, evSort, 0);
    edge_gate_kernel<<<444, F_THR, F_SMEM, 0>>>(ea, Wffw, bffw, bf, bs, z_edge, z_node);
}